// round 6
// baseline (speedup 1.0000x reference)
#include <cuda_runtime.h>
#include <cuda_bf16.h>
#include <mma.h>

using namespace nvcuda;

#define B_  64
#define S_  197
#define D_  1024
#define H_  4096
#define MROWS (B_ * S_)          // 12608
#define MTILES 99
#define MPAD (MTILES * 128)      // 12672

// ---------------- scratch (static device globals; no allocations) ----------
__device__ __nv_bfloat16 g_xa [(size_t)MPAD * D_];       // x as bf16, padded
__device__ __nv_bfloat16 g_w1b[(size_t)H_ * D_];         // quantized w1 (bf16 ints)
__device__ __nv_bfloat16 g_w2b[(size_t)D_ * H_];         // quantized w2
__device__ float         g_acc1[(size_t)MPAD * H_];      // GEMM1 acc, then gelu(g)
__device__ __nv_bfloat16 g_q  [(size_t)MPAD * H_];       // requantized act, padded
__device__ float         g_out2[(size_t)MPAD * D_];      // GEMM2 acc (padded)
__device__ float         g_b1i[H_];
__device__ float         g_b2i[D_];
__device__ unsigned      g_w1max, g_w2max, g_xhmax;
// c[0]=b_int c[1]=c_int c[2]=-b_int c[3]=shift_int c[4]=gelu_sf
// c[5]=s_w1  c[6]=s_out1 c[7]=s_w2  c[8]=s_a  c[9]=s_out2
__device__ float         g_c[12];

// ---------------- small kernels --------------------------------------------
__global__ void k_init() {
    g_w1max = 0u; g_w2max = 0u; g_xhmax = 0u;
}

__global__ void k_absmax(const float* __restrict__ w, int n, int which) {
    float m = 0.f;
    for (int i = blockIdx.x * blockDim.x + threadIdx.x; i < n;
         i += gridDim.x * blockDim.x)
        m = fmaxf(m, fabsf(w[i]));
    #pragma unroll
    for (int o = 16; o; o >>= 1) m = fmaxf(m, __shfl_xor_sync(~0u, m, o));
    __shared__ float sm[32];
    if ((threadIdx.x & 31) == 0) sm[threadIdx.x >> 5] = m;
    __syncthreads();
    if (threadIdx.x < 32) {
        m = (threadIdx.x < (blockDim.x >> 5)) ? sm[threadIdx.x] : 0.f;
        #pragma unroll
        for (int o = 16; o; o >>= 1) m = fmaxf(m, __shfl_xor_sync(~0u, m, o));
        if (threadIdx.x == 0)
            atomicMax(which ? &g_w2max : &g_w1max, __float_as_uint(m));
    }
}

__global__ void k_consts1(const float* __restrict__ sx_p) {
    float sw1 = __fdiv_rn(__uint_as_float(g_w1max), 127.0f);
    float sw2 = __fdiv_rn(__uint_as_float(g_w2max), 127.0f);
    float sx  = sx_p[0];
    float s1  = __fmul_rn(sx, sw1);                 // s_out of linear1
    float sfe = __fdiv_rn(s1, 1.4142f);             // sf / sqrt(2)
    float bint = floorf(__fdiv_rn(-1.769f, sfe));
    float sf2  = __fmul_rn(sfe, sfe);
    const float cC = (float)(1.0 / -0.2888);        // COEF_C rounded to f32
    float cint = floorf(__fdiv_rn(cC, sf2));
    float sig_sf = __fmul_rn(__fmul_rn(sf2, -0.2888f), 16384.0f);
    float shift  = floorf(__fdiv_rn(1.0f, sig_sf));
    float gelu_sf = __fmul_rn(__fmul_rn(s1, sig_sf), 0.5f);
    g_c[0] = bint; g_c[1] = cint; g_c[2] = -bint; g_c[3] = shift;
    g_c[4] = gelu_sf; g_c[5] = sw1; g_c[6] = s1; g_c[7] = sw2;
}

__global__ void k_quantw(const float* __restrict__ w, int n, int which) {
    float sw = g_c[which ? 7 : 5];
    __nv_bfloat16* dst = which ? g_w2b : g_w1b;
    for (int i = blockIdx.x * blockDim.x + threadIdx.x; i < n;
         i += gridDim.x * blockDim.x) {
        float q = rintf(__fdiv_rn(w[i], sw));       // round half-to-even
        q = fminf(fmaxf(q, -127.f), 127.f);
        dst[i] = __float2bfloat16_rn(q);            // exact (|q| <= 127)
    }
}

__global__ void k_quantb(const float* __restrict__ b, int n, int which) {
    float s = g_c[which ? 9 : 6];
    float* dst = which ? g_b2i : g_b1i;
    for (int i = blockIdx.x * blockDim.x + threadIdx.x; i < n;
         i += gridDim.x * blockDim.x)
        dst[i] = rintf(__fdiv_rn(b[i], s));
}

__global__ void k_xconv(const int* __restrict__ x) {
    const size_t nv = (size_t)MROWS * D_;
    const size_t n  = (size_t)MPAD * D_;
    size_t stride = (size_t)gridDim.x * blockDim.x;
    for (size_t i = (size_t)blockIdx.x * blockDim.x + threadIdx.x; i < n;
         i += stride)
        g_xa[i] = (i < nv) ? __float2bfloat16_rn((float)x[i])
                           : __float2bfloat16_rn(0.f);
}

// ---------------- wmma bf16 GEMM -------------------------------------------
// C[MPAD, N] = A[MPAD, K] * B[N, K]^T   (all bf16 integer values, f32 acc)
// block tile 128x128, BK=32, 8 warps (4 along M, 2 along N), each warp 32x64.
template <int K, int N, int WHICH>
__global__ void __launch_bounds__(256) k_gemm() {
    const __nv_bfloat16* __restrict__ A  = WHICH ? g_q   : g_xa;
    const __nv_bfloat16* __restrict__ Bm = WHICH ? g_w2b : g_w1b;
    float* __restrict__ C = WHICH ? g_out2 : g_acc1;

    __shared__ __nv_bfloat16 As[128][40];
    __shared__ __nv_bfloat16 Bs[128][40];

    int tid  = threadIdx.x;
    int warp = tid >> 5;
    int wm   = warp >> 1;          // 0..3
    int wn   = warp & 1;           // 0..1
    size_t m0 = (size_t)blockIdx.y * 128;
    size_t n0 = (size_t)blockIdx.x * 128;

    wmma::fragment<wmma::accumulator, 16, 16, 16, float> acc[2][4];
    #pragma unroll
    for (int i = 0; i < 2; i++)
        #pragma unroll
        for (int j = 0; j < 4; j++) wmma::fill_fragment(acc[i][j], 0.f);

    int r0 = tid >> 2;             // 0..63  (row within first half)
    int cv = (tid & 3) * 8;        // 0,8,16,24

    for (int kt = 0; kt < K; kt += 32) {
        #pragma unroll
        for (int t = 0; t < 2; t++) {
            int row = r0 + t * 64;
            const uint4* pa = reinterpret_cast<const uint4*>(
                A + (m0 + row) * (size_t)K + kt + cv);
            *reinterpret_cast<uint4*>(&As[row][cv]) = *pa;
            const uint4* pb = reinterpret_cast<const uint4*>(
                Bm + (n0 + row) * (size_t)K + kt + cv);
            *reinterpret_cast<uint4*>(&Bs[row][cv]) = *pb;
        }
        __syncthreads();
        #pragma unroll
        for (int ks = 0; ks < 2; ks++) {
            wmma::fragment<wmma::matrix_a, 16, 16, 16, __nv_bfloat16,
                           wmma::row_major> af[2];
            wmma::fragment<wmma::matrix_b, 16, 16, 16, __nv_bfloat16,
                           wmma::col_major> bf[4];
            #pragma unroll
            for (int i = 0; i < 2; i++)
                wmma::load_matrix_sync(af[i], &As[wm * 32 + i * 16][ks * 16], 40);
            #pragma unroll
            for (int j = 0; j < 4; j++)
                wmma::load_matrix_sync(bf[j], &Bs[wn * 64 + j * 16][ks * 16], 40);
            #pragma unroll
            for (int i = 0; i < 2; i++)
                #pragma unroll
                for (int j = 0; j < 4; j++)
                    wmma::mma_sync(acc[i][j], af[i], bf[j], acc[i][j]);
        }
        __syncthreads();
    }

    #pragma unroll
    for (int i = 0; i < 2; i++)
        #pragma unroll
        for (int j = 0; j < 4; j++)
            wmma::store_matrix_sync(
                C + (m0 + wm * 32 + i * 16) * (size_t)N + n0 + wn * 64 + j * 16,
                acc[i][j], N, wmma::mem_row_major);
}

// ---------------- GELU (I-BERT exact f32 sequence) + global max ------------
__global__ void k_gelu() {
    const float bint = g_c[0], cint = g_c[1], mb = g_c[2],
                shift = g_c[3], gsf = g_c[4];
    float mloc = 0.f;
    const size_t n = (size_t)MROWS * H_;
    size_t stride = (size_t)gridDim.x * blockDim.x;
    for (size_t i = (size_t)blockIdx.x * blockDim.x + threadIdx.x; i < n;
         i += stride) {
        float x = __fadd_rn(g_acc1[i], g_b1i[i & (H_ - 1)]);  // exact ints
        float sg = (x > 0.f) ? 1.f : ((x < 0.f) ? -1.f : 0.f);
        float ax = fminf(fabsf(x), mb);
        float t  = __fadd_rn(ax, bint);
        float y  = __fmul_rn(sg, __fadd_rn(__fmul_rn(t, t), cint));
        float sig = floorf(__fmul_rn(y, 6.103515625e-05f));   // /2^14 exact
        float g = __fmul_rn(x, __fadd_rn(sig, shift));
        g_acc1[i] = g;
        mloc = fmaxf(mloc, fabsf(__fmul_rn(g, gsf)));         // per-elem x_hat
    }
    #pragma unroll
    for (int o = 16; o; o >>= 1) mloc = fmaxf(mloc, __shfl_xor_sync(~0u, mloc, o));
    __shared__ float sm[32];
    if ((threadIdx.x & 31) == 0) sm[threadIdx.x >> 5] = mloc;
    __syncthreads();
    if (threadIdx.x < 32) {
        mloc = (threadIdx.x < (blockDim.x >> 5)) ? sm[threadIdx.x] : 0.f;
        #pragma unroll
        for (int o = 16; o; o >>= 1) mloc = fmaxf(mloc, __shfl_xor_sync(~0u, mloc, o));
        if (threadIdx.x == 0) atomicMax(&g_xhmax, __float_as_uint(mloc));
    }
}

__global__ void k_consts2() {
    float sa = __fdiv_rn(__uint_as_float(g_xhmax), 127.0f);
    g_c[8] = sa;
    g_c[9] = __fmul_rn(sa, g_c[7]);     // s_out2 = s_a * s_w2
}

__global__ void k_requant() {
    const float sa = g_c[8], gsf = g_c[4];
    const size_t nv = (size_t)MROWS * H_;
    const size_t n  = (size_t)MPAD * H_;
    size_t stride = (size_t)gridDim.x * blockDim.x;
    for (size_t i = (size_t)blockIdx.x * blockDim.x + threadIdx.x; i < n;
         i += stride) {
        float q = 0.f;
        if (i < nv) {
            float xh = __fmul_rn(g_acc1[i], gsf);
            q = fminf(fmaxf(rintf(__fdiv_rn(xh, sa)), -128.f), 127.f);
        }
        g_q[i] = __float2bfloat16_rn(q);    // exact (|q| <= 128)
    }
}

__global__ void k_final(float* __restrict__ out, int out_size) {
    const float s2 = g_c[9];
    const size_t nv = (size_t)MROWS * D_;
    size_t stride = (size_t)gridDim.x * blockDim.x;
    for (size_t i = (size_t)blockIdx.x * blockDim.x + threadIdx.x;
         i < (size_t)out_size; i += stride)
        out[i] = (i < nv) ? __fadd_rn(g_out2[i], g_b2i[i & (D_ - 1)]) : s2;
}

// ---------------- launcher --------------------------------------------------
extern "C" void kernel_launch(void* const* d_in, const int* in_sizes, int n_in,
                              void* d_out, int out_size) {
    const int*   x  = (const int*)  d_in[0];
    const float* sx = (const float*)d_in[1];
    const float* w1 = (const float*)d_in[2];
    const float* b1 = (const float*)d_in[3];
    const float* w2 = (const float*)d_in[4];
    const float* b2 = (const float*)d_in[5];
    float* out = (float*)d_out;

    k_init<<<1, 1>>>();
    k_absmax<<<512, 256>>>(w1, H_ * D_, 0);
    k_absmax<<<512, 256>>>(w2, D_ * H_, 1);
    k_consts1<<<1, 1>>>(sx);
    k_quantw<<<2048, 256>>>(w1, H_ * D_, 0);
    k_quantw<<<2048, 256>>>(w2, D_ * H_, 1);
    k_quantb<<<16, 256>>>(b1, H_, 0);
    k_xconv<<<4096, 256>>>(x);

    k_gemm<D_, H_, 0><<<dim3(H_ / 128, MTILES), 256>>>();   // GEMM1
    k_gelu<<<8192, 256>>>();
    k_consts2<<<1, 1>>>();
    k_quantb<<<4, 256>>>(b2, D_, 1);
    k_requant<<<8192, 256>>>();
    k_gemm<H_, D_, 1><<<dim3(D_ / 128, MTILES), 256>>>();   // GEMM2
    k_final<<<8192, 256>>>(out, out_size);
}